// round 16
// baseline (speedup 1.0000x reference)
#include <cuda_runtime.h>
#include <math.h>

#define Bq 64
#define Sq 256
#define Tq 128
#define Hq 512
#define Eq 512
#define G4q 2048

typedef unsigned long long ull;

// ---------------- scratch (static device memory; no allocations) ----------------
__device__ float g_xW[(size_t)Bq * Sq * G4q];     // x@W_ih^T + b_ih + b_hh, per (b,s)
__device__ float g_enc[(size_t)Bq * Sq * Hq];     // encoder hidden states (b*S+s, h)
__device__ float g_encpart[(size_t)Bq * Sq * Hq]; // enc_outs @ W1_enc^T + b1
__device__ float g_qbuf[(size_t)Bq * Tq * Hq];    // dec_h @ W1_dec^T
__device__ float g_hA[Bq * Hq];
__device__ float g_hB[Bq * Hq];
__device__ int   g_bar[4 * 384];                  // per m-group, per step arrival counters

__device__ __forceinline__ float sigmoidf_(float x) { return 1.0f / (1.0f + expf(-x)); }

__device__ __forceinline__ void fma2(ull& d, ull a, ull b) {
    asm("fma.rn.f32x2 %0, %1, %2, %0;" : "+l"(d) : "l"(a), "l"(b));
}
__device__ __forceinline__ float hsum2(ull a) {
    float lo = __uint_as_float((unsigned)(a & 0xffffffffu));
    float hi = __uint_as_float((unsigned)(a >> 32));
    return lo + hi;
}

// ---------------- init: broadcast h0 into hA; zero step barriers ----------------
__global__ void init_state_kernel(const float* __restrict__ h0) {
    int i = blockIdx.x * blockDim.x + threadIdx.x;
    if (i < Bq * Hq) g_hA[i] = h0[i & (Hq - 1)];
    int b = i - Bq * Hq;
    if (b >= 0 && b < 4 * 384) g_bar[b] = 0;
}

// ---------------- fp32 GEMM, 128x128 tile, BK=16 double-buffered, 8x8 split tile ----
//  C[m,n] = sum_k A[row(m),k] * Wt[n,k] + bias(+bias2)
// 256 threads, 2 CTAs/SM (regs capped at 124 so two 32.5K-reg CTAs fit the 64K RF).
__global__ __launch_bounds__(256, 2) void gemm_bias(
    const float* __restrict__ A, const float* __restrict__ Wt,
    const int* __restrict__ rows,
    const float* __restrict__ bias, const float* __restrict__ bias2,
    float* __restrict__ C, int K, int ldb, int ldc)
{
    __shared__ __align__(16) float As[2][16][128];
    __shared__ __align__(16) float Bs[2][16][128];

    int m0 = blockIdx.x * 128;
    int n0 = blockIdx.y * 128;
    int t  = threadIdx.x;
    int ty = t >> 4;
    int tx = t & 15;

    float aLL[4][4], aLH[4][4], aHL[4][4], aHH[4][4];
#pragma unroll
    for (int i = 0; i < 4; i++)
#pragma unroll
        for (int j = 0; j < 4; j++) {
            aLL[i][j] = 0.f; aLH[i][j] = 0.f; aHL[i][j] = 0.f; aHH[i][j] = 0.f;
        }

    int aRow = t >> 1;            // 0..127
    int aCol = (t & 1) * 8;       // 0 or 8
    long arow = rows ? (long)rows[m0 + aRow] : (long)(m0 + aRow);
    const float* Aptr = A + arow * (long)K + aCol;
    const float* Bptr = Wt + (long)(n0 + aRow) * ldb + aCol;

    const int nk = K / 16;
    float4 aF0 = *(const float4*)(Aptr);
    float4 aF1 = *(const float4*)(Aptr + 4);
    float4 bF0 = *(const float4*)(Bptr);
    float4 bF1 = *(const float4*)(Bptr + 4);

    As[0][aCol + 0][aRow] = aF0.x; As[0][aCol + 1][aRow] = aF0.y;
    As[0][aCol + 2][aRow] = aF0.z; As[0][aCol + 3][aRow] = aF0.w;
    As[0][aCol + 4][aRow] = aF1.x; As[0][aCol + 5][aRow] = aF1.y;
    As[0][aCol + 6][aRow] = aF1.z; As[0][aCol + 7][aRow] = aF1.w;
    Bs[0][aCol + 0][aRow] = bF0.x; Bs[0][aCol + 1][aRow] = bF0.y;
    Bs[0][aCol + 2][aRow] = bF0.z; Bs[0][aCol + 3][aRow] = bF0.w;
    Bs[0][aCol + 4][aRow] = bF1.x; Bs[0][aCol + 5][aRow] = bF1.y;
    Bs[0][aCol + 6][aRow] = bF1.z; Bs[0][aCol + 7][aRow] = bF1.w;
    __syncthreads();

    int buf = 0;
    for (int kb = 0; kb < nk; ++kb) {
        if (kb + 1 < nk) {
            const float* ap = Aptr + (kb + 1) * 16;
            const float* bp = Bptr + (kb + 1) * 16;
            aF0 = *(const float4*)(ap);
            aF1 = *(const float4*)(ap + 4);
            bF0 = *(const float4*)(bp);
            bF1 = *(const float4*)(bp + 4);
        }
#pragma unroll
        for (int kk = 0; kk < 16; ++kk) {
            float4 a0 = *(const float4*)&As[buf][kk][ty * 4];
            float4 a1 = *(const float4*)&As[buf][kk][64 + ty * 4];
            float4 b0 = *(const float4*)&Bs[buf][kk][tx * 4];
            float4 b1 = *(const float4*)&Bs[buf][kk][64 + tx * 4];
            float am0[4] = {a0.x, a0.y, a0.z, a0.w};
            float am1[4] = {a1.x, a1.y, a1.z, a1.w};
            float bn0[4] = {b0.x, b0.y, b0.z, b0.w};
            float bn1[4] = {b1.x, b1.y, b1.z, b1.w};
#pragma unroll
            for (int i = 0; i < 4; i++)
#pragma unroll
                for (int j = 0; j < 4; j++) {
                    aLL[i][j] = fmaf(am0[i], bn0[j], aLL[i][j]);
                    aLH[i][j] = fmaf(am0[i], bn1[j], aLH[i][j]);
                    aHL[i][j] = fmaf(am1[i], bn0[j], aHL[i][j]);
                    aHH[i][j] = fmaf(am1[i], bn1[j], aHH[i][j]);
                }
        }
        if (kb + 1 < nk) {
            int nb = buf ^ 1;
            As[nb][aCol + 0][aRow] = aF0.x; As[nb][aCol + 1][aRow] = aF0.y;
            As[nb][aCol + 2][aRow] = aF0.z; As[nb][aCol + 3][aRow] = aF0.w;
            As[nb][aCol + 4][aRow] = aF1.x; As[nb][aCol + 5][aRow] = aF1.y;
            As[nb][aCol + 6][aRow] = aF1.z; As[nb][aCol + 7][aRow] = aF1.w;
            Bs[nb][aCol + 0][aRow] = bF0.x; Bs[nb][aCol + 1][aRow] = bF0.y;
            Bs[nb][aCol + 2][aRow] = bF0.z; Bs[nb][aCol + 3][aRow] = bF0.w;
            Bs[nb][aCol + 4][aRow] = bF1.x; Bs[nb][aCol + 5][aRow] = bF1.y;
            Bs[nb][aCol + 6][aRow] = bF1.z; Bs[nb][aCol + 7][aRow] = bF1.w;
            __syncthreads();
            buf = nb;
        }
    }

    float bbL[4], bbH[4];
#pragma unroll
    for (int j = 0; j < 4; j++) {
        int nL = n0 + tx * 4 + j;
        int nH = nL + 64;
        float vL = 0.f, vH = 0.f;
        if (bias)  { vL += bias[nL];  vH += bias[nH]; }
        if (bias2) { vL += bias2[nL]; vH += bias2[nH]; }
        bbL[j] = vL; bbH[j] = vH;
    }
#pragma unroll
    for (int i = 0; i < 4; i++) {
        long rowL = (long)(m0 + ty * 4 + i) * ldc + n0 + tx * 4;
        long rowH = (long)(m0 + 64 + ty * 4 + i) * ldc + n0 + tx * 4;
        float4 oLL = make_float4(aLL[i][0] + bbL[0], aLL[i][1] + bbL[1],
                                 aLL[i][2] + bbL[2], aLL[i][3] + bbL[3]);
        float4 oLH = make_float4(aLH[i][0] + bbH[0], aLH[i][1] + bbH[1],
                                 aLH[i][2] + bbH[2], aLH[i][3] + bbH[3]);
        float4 oHL = make_float4(aHL[i][0] + bbL[0], aHL[i][1] + bbL[1],
                                 aHL[i][2] + bbL[2], aHL[i][3] + bbL[3]);
        float4 oHH = make_float4(aHH[i][0] + bbH[0], aHH[i][1] + bbH[1],
                                 aHH[i][2] + bbH[2], aHH[i][3] + bbH[3]);
        *(float4*)&C[rowL]      = oLL;
        *(float4*)&C[rowL + 64] = oLH;
        *(float4*)&C[rowH]      = oHL;
        *(float4*)&C[rowH + 64] = oHH;
    }
}

// ---------------- persistent fused LSTM recurrence (register-tiled, R10 compute) -----
// Grid: 128 CTAs x 256 threads. CTA (mb, jb): m-block = 16 batches, j-slice = 16 cols.
// Compute thread (ks, jj, mb2): 4 gates x 4 m over k-quarter ks; partials in ex[4][64*17].
#define WSTR 516
#define EXSZ (64 * 17)
#define SMEM_PERS ((64 * WSTR + 16 * WSTR + 4 * EXSZ) * 4)

__device__ __forceinline__ void load_wslice(float* ws, const float* __restrict__ W,
                                            int j0, int tid) {
    for (int idx = tid; idx < 64 * 128; idx += 256) {
        int r = idx >> 7;          // 0..63
        int k16 = idx & 127;       // float4 index
        int n = (r >> 4) * Hq + j0 + (r & 15);
        float4 v = *(const float4*)(W + (size_t)n * Hq + k16 * 4);
        *(float4*)(ws + r * WSTR + k16 * 4) = v;
    }
}

__global__ __launch_bounds__(256, 1) void lstm_persistent(
    const float* __restrict__ xW,
    const float* __restrict__ eWhh, const float* __restrict__ dWhh,
    const float* __restrict__ dbih, const float* __restrict__ dbhh,
    const float* __restrict__ c0,
    float* __restrict__ enc, float* __restrict__ dec_out)
{
    extern __shared__ float smem[];
    float* ws = smem;
    float* hs = smem + 64 * WSTR;
    float* ex = smem + 64 * WSTR + 16 * WSTR;      // 4 k-quarter buffers of 64*17

    int tid = threadIdx.x;
    int bx = blockIdx.x;
    int mb = bx >> 5;          // 0..3  (m-group)
    int jb = bx & 31;          // 0..31
    int j0 = jb * 16;

    // compute-role mapping: ks = k-quarter, jj = gate column, mb2 = m phase
    int lane = tid & 31, wrp = tid >> 5;
    int ks = wrp >> 1;                           // 0..3
    int jj = ((wrp & 1) << 3) + (lane >> 2);     // 0..15
    int mb2 = lane & 3;                          // 0..3
    int kbase = ks * 32;                         // ulonglong2 offset into k
    const ulonglong2* wr0 = (const ulonglong2*)(ws + (0 * 16 + jj) * WSTR) + kbase;
    const ulonglong2* wr1 = (const ulonglong2*)(ws + (1 * 16 + jj) * WSTR) + kbase;
    const ulonglong2* wr2 = (const ulonglong2*)(ws + (2 * 16 + jj) * WSTR) + kbase;
    const ulonglong2* wr3 = (const ulonglong2*)(ws + (3 * 16 + jj) * WSTR) + kbase;
    const ulonglong2* hm0 = (const ulonglong2*)(hs + (mb2 + 0) * WSTR) + kbase;
    const ulonglong2* hm1 = (const ulonglong2*)(hs + (mb2 + 4) * WSTR) + kbase;
    const ulonglong2* hm2 = (const ulonglong2*)(hs + (mb2 + 8) * WSTR) + kbase;
    const ulonglong2* hm3 = (const ulonglong2*)(hs + (mb2 + 12) * WSTR) + kbase;
    float* exk = ex + ks * EXSZ;

    // epilogue-role mapping
    int em = tid >> 4;         // 0..15 local m
    int ejj = tid & 15;        // 0..15 local j
    int j = j0 + ejj;
    int mg = mb * 16 + em;     // global batch index
    float c_reg = c0[j];
    float bi = 0.f, bf = 0.f, bg = 0.f, bo = 0.f;

    load_wslice(ws, eWhh, j0, tid);

    for (int step = 0; step < Sq + Tq; ++step) {
        const bool encp = (step < Sq);
        if (step == Sq) {
            __syncthreads();
            load_wslice(ws, dWhh, j0, tid);
            bi = dbih[j]           + dbhh[j];
            bf = dbih[Hq + j]      + dbhh[Hq + j];
            bg = dbih[2 * Hq + j]  + dbhh[2 * Hq + j];
            bo = dbih[3 * Hq + j]  + dbhh[3 * Hq + j];
        }
        const float* hcur = (step & 1) ? g_hB : g_hA;
        float*       hnxt = (step & 1) ? g_hA : g_hB;

        // stage this m-block's h rows into smem (full 512 floats/row: 2048 float4s)
        {
            const float* src = hcur + (size_t)mb * 16 * Hq;
#pragma unroll
            for (int rr = 0; rr < 8; ++rr) {
                int lin = tid + 256 * rr;     // float4 slot 0..2047
                int row = lin >> 7;           // 0..15
                int c4  = lin & 127;          // 0..127
                float4 v = *(const float4*)(src + (size_t)row * Hq + c4 * 4);
                *(float4*)(hs + row * WSTR + c4 * 4) = v;
            }
        }
        // prefetch per-step additive term (xW for encoder, bias for decoder)
        float xw0, xw1, xw2, xw3;
        if (encp) {
            const float* xr = xW + ((size_t)mg * Sq + step) * G4q + j;
            xw0 = xr[0]; xw1 = xr[Hq]; xw2 = xr[2 * Hq]; xw3 = xr[3 * Hq];
        } else {
            xw0 = bi; xw1 = bf; xw2 = bg; xw3 = bo;
        }
        __syncthreads();

        // register tile: acc[g][i] over k-quarter; 8 LDS.128 + 32 FFMA2 per iter
        {
            ull acc[4][4];
#pragma unroll
            for (int g = 0; g < 4; g++)
#pragma unroll
                for (int i = 0; i < 4; i++) acc[g][i] = 0;

#pragma unroll 8
            for (int kk = 0; kk < 32; ++kk) {
                ulonglong2 wv0 = wr0[kk];
                ulonglong2 wv1 = wr1[kk];
                ulonglong2 wv2 = wr2[kk];
                ulonglong2 wv3 = wr3[kk];
                ulonglong2 hv0 = hm0[kk];
                ulonglong2 hv1 = hm1[kk];
                ulonglong2 hv2 = hm2[kk];
                ulonglong2 hv3 = hm3[kk];
                fma2(acc[0][0], hv0.x, wv0.x); fma2(acc[0][0], hv0.y, wv0.y);
                fma2(acc[0][1], hv1.x, wv0.x); fma2(acc[0][1], hv1.y, wv0.y);
                fma2(acc[0][2], hv2.x, wv0.x); fma2(acc[0][2], hv2.y, wv0.y);
                fma2(acc[0][3], hv3.x, wv0.x); fma2(acc[0][3], hv3.y, wv0.y);
                fma2(acc[1][0], hv0.x, wv1.x); fma2(acc[1][0], hv0.y, wv1.y);
                fma2(acc[1][1], hv1.x, wv1.x); fma2(acc[1][1], hv1.y, wv1.y);
                fma2(acc[1][2], hv2.x, wv1.x); fma2(acc[1][2], hv2.y, wv1.y);
                fma2(acc[1][3], hv3.x, wv1.x); fma2(acc[1][3], hv3.y, wv1.y);
                fma2(acc[2][0], hv0.x, wv2.x); fma2(acc[2][0], hv0.y, wv2.y);
                fma2(acc[2][1], hv1.x, wv2.x); fma2(acc[2][1], hv1.y, wv2.y);
                fma2(acc[2][2], hv2.x, wv2.x); fma2(acc[2][2], hv2.y, wv2.y);
                fma2(acc[2][3], hv3.x, wv2.x); fma2(acc[2][3], hv3.y, wv2.y);
                fma2(acc[3][0], hv0.x, wv3.x); fma2(acc[3][0], hv0.y, wv3.y);
                fma2(acc[3][1], hv1.x, wv3.x); fma2(acc[3][1], hv1.y, wv3.y);
                fma2(acc[3][2], hv2.x, wv3.x); fma2(acc[3][2], hv2.y, wv3.y);
                fma2(acc[3][3], hv3.x, wv3.x); fma2(acc[3][3], hv3.y, wv3.y);
            }
            // write partials: exk[(g*16+jj)*17 + m], m = mb2 + 4i
#pragma unroll
            for (int g = 0; g < 4; g++)
#pragma unroll
                for (int i = 0; i < 4; i++)
                    exk[(g * 16 + jj) * 17 + (mb2 + 4 * i)] = hsum2(acc[g][i]);
        }
        __syncthreads();

        // epilogue: thread (em, ejj); combine 4 k-quarters
        {
            int i0 = (0 * 16 + ejj) * 17 + em;
            int i1 = (1 * 16 + ejj) * 17 + em;
            int i2 = (2 * 16 + ejj) * 17 + em;
            int i3 = (3 * 16 + ejj) * 17 + em;
            float vi = (ex[i0] + ex[i0 + EXSZ]) + (ex[i0 + 2 * EXSZ] + ex[i0 + 3 * EXSZ]) + xw0;
            float vf = (ex[i1] + ex[i1 + EXSZ]) + (ex[i1 + 2 * EXSZ] + ex[i1 + 3 * EXSZ]) + xw1;
            float vg = (ex[i2] + ex[i2 + EXSZ]) + (ex[i2 + 2 * EXSZ] + ex[i2 + 3 * EXSZ]) + xw2;
            float vo = (ex[i3] + ex[i3 + EXSZ]) + (ex[i3 + 2 * EXSZ] + ex[i3 + 3 * EXSZ]) + xw3;
            float cn = sigmoidf_(vf) * c_reg + sigmoidf_(vi) * tanhf(vg);
            float hn = sigmoidf_(vo) * tanhf(cn);
            c_reg = cn;
            hnxt[(size_t)mg * Hq + j] = hn;
            if (encp) enc[((size_t)mg * Sq + step) * Hq + j] = hn;
            else      dec_out[((size_t)mg * Tq + (step - Sq)) * Hq + j] = hn;
        }

        if (step == Sq + Tq - 1) break;   // nothing reads the final h: skip barrier

        // group barrier (32 CTAs sharing this m-block)
        __syncthreads();
        if (tid == 0) {
            int* bar = &g_bar[mb * 384 + step];
            asm volatile("red.release.gpu.global.add.s32 [%0], 1;" :: "l"(bar) : "memory");
            int v;
            do {
                asm volatile("ld.acquire.gpu.global.b32 %0, [%1];" : "=r"(v) : "l"(bar) : "memory");
            } while (v < 32);
        }
        __syncthreads();
    }
}

// ---------------- scoring: score[b,t,s] = b2 + sum_h W2[h]*relu(encpart[b,s,h]+q[b,t,h]) ----
__global__ __launch_bounds__(256) void score_kernel(
    const float* __restrict__ encpart, const float* __restrict__ q,
    const float* __restrict__ W2, const float* __restrict__ b2,
    float* __restrict__ out)
{
    __shared__ __align__(16) float qs[16][512];
    int b = blockIdx.y;
    int s0 = blockIdx.x * 16;
    int t = threadIdx.x;
    int warp = t >> 5;
    int lane = t & 31;

    float w2r[16], e0[16], e1[16];
    const float* ep = encpart + ((long)b * Sq + s0 + warp * 2) * Hq;
#pragma unroll
    for (int i = 0; i < 16; i++) {
        w2r[i] = W2[lane + 32 * i];
        e0[i] = ep[lane + 32 * i];
        e1[i] = ep[Hq + lane + 32 * i];
    }
    float b2v = b2[0];

    for (int tc = 0; tc < Tq / 16; ++tc) {
        __syncthreads();
        const float* qp = q + ((long)b * Tq + tc * 16) * Hq;
#pragma unroll
        for (int rr = 0; rr < 8; rr++) {
            int lin = t + 256 * rr;
            int tt = lin >> 7;
            int off = (lin & 127) * 4;
            *(float4*)&qs[tt][off] = *(const float4*)(qp + (long)tt * Hq + off);
        }
        __syncthreads();
#pragma unroll 4
        for (int tt = 0; tt < 16; ++tt) {
            float a0 = 0.0f, a1 = 0.0f;
#pragma unroll
            for (int i = 0; i < 16; i++) {
                float qv = qs[tt][lane + 32 * i];
                float v0 = fmaxf(e0[i] + qv, 0.0f);
                float v1 = fmaxf(e1[i] + qv, 0.0f);
                a0 = fmaf(v0, w2r[i], a0);
                a1 = fmaf(v1, w2r[i], a1);
            }
#pragma unroll
            for (int o = 16; o; o >>= 1) {
                a0 += __shfl_xor_sync(0xffffffffu, a0, o);
                a1 += __shfl_xor_sync(0xffffffffu, a1, o);
            }
            if (lane == 0) {
                long row = ((long)b * Tq + tc * 16 + tt) * Sq + s0 + warp * 2;
                out[row] = a0 + b2v;
                out[row + 1] = a1 + b2v;
            }
        }
    }
}

// ---------------- masked log_softmax over s (in place); mask is int32 ----------------
__global__ __launch_bounds__(256) void lsm_kernel(float* __restrict__ io,
                                                  const int* __restrict__ mask)
{
    int row = blockIdx.x * 8 + (threadIdx.x >> 5);
    int lane = threadIdx.x & 31;
    int b = row / Tq;
    const int* mrow = mask + (long)b * Sq;
    float* x = io + (long)row * Sq;

    float v[8];
    float mx = -INFINITY;
#pragma unroll
    for (int i = 0; i < 8; i++) {
        int s = lane + 32 * i;
        float xv = x[s];
        v[i] = (mrow[s] != 0) ? xv : -INFINITY;
        mx = fmaxf(mx, v[i]);
    }
#pragma unroll
    for (int o = 16; o; o >>= 1) mx = fmaxf(mx, __shfl_xor_sync(0xffffffffu, mx, o));
    float sum = 0.0f;
#pragma unroll
    for (int i = 0; i < 8; i++) sum += expf(v[i] - mx);
#pragma unroll
    for (int o = 16; o; o >>= 1) sum += __shfl_xor_sync(0xffffffffu, sum, o);
    float lse = mx + logf(sum);
#pragma unroll
    for (int i = 0; i < 8; i++) {
        int s = lane + 32 * i;
        x[s] = v[i] - lse;
    }
}

// ---------------- launch ----------------
extern "C" void kernel_launch(void* const* d_in, const int* in_sizes, int n_in,
                              void* d_out, int out_size)
{
    const int*   state = (const int*)d_in[0];
    const int*   mask  = (const int*)d_in[1];
    const float* emb  = (const float*)d_in[3];
    const float* eWih = (const float*)d_in[4];
    const float* eWhh = (const float*)d_in[5];
    const float* ebih = (const float*)d_in[6];
    const float* ebhh = (const float*)d_in[7];
    const float* h0   = (const float*)d_in[8];
    const float* c0   = (const float*)d_in[9];
    const float* dWhh = (const float*)d_in[11];
    const float* dbih = (const float*)d_in[12];
    const float* dbhh = (const float*)d_in[13];
    const float* W1   = (const float*)d_in[14];
    const float* b1   = (const float*)d_in[15];
    const float* W2   = (const float*)d_in[16];
    const float* b2   = (const float*)d_in[17];

    float* out_logits = (float*)d_out;
    float* out_dec    = out_logits + (size_t)Bq * Tq * Sq;

    float *xW, *enc, *encpart, *q;
    cudaGetSymbolAddress((void**)&xW, g_xW);
    cudaGetSymbolAddress((void**)&enc, g_enc);
    cudaGetSymbolAddress((void**)&encpart, g_encpart);
    cudaGetSymbolAddress((void**)&q, g_qbuf);

    static int smem_set = 0;
    if (!smem_set) {
        cudaFuncSetAttribute(lstm_persistent,
                             cudaFuncAttributeMaxDynamicSharedMemorySize, SMEM_PERS);
        smem_set = 1;
    }

    // 1. init h (broadcast) + zero barriers
    init_state_kernel<<<(Bq * Hq + 4 * 384 + 255) / 256, 256>>>(h0);

    // 2. xW = emb[state] @ enc_W_ih^T + (b_ih + b_hh)     (M=16384, N=2048, K=512)
    gemm_bias<<<dim3((Bq * Sq) / 128, G4q / 128), 256>>>(
        emb, eWih, state, ebih, ebhh, xW, Eq, Eq, G4q);

    // 3+5. full recurrence (256 encoder + 128 decoder steps) in one persistent kernel
    lstm_persistent<<<128, 256, SMEM_PERS>>>(xW, eWhh, dWhh, dbih, dbhh, c0,
                                             enc, out_dec);

    // 4. enc_part = enc_outs @ W1_enc^T + b1   (M=16384, N=512, K=512; W1 ld=1024)
    gemm_bias<<<dim3((Bq * Sq) / 128, Hq / 128), 256>>>(
        enc, W1, nullptr, b1, nullptr, encpart, Hq, Hq * 2, Hq);

    // 6. q = dec_hs @ W1_dec^T                 (M=8192, N=512, K=512)
    gemm_bias<<<dim3((Bq * Tq) / 128, Hq / 128), 256>>>(
        out_dec, W1 + Hq, nullptr, nullptr, nullptr, q, Hq, Hq * 2, Hq);

    // 7. scores -> out_logits (raw)
    score_kernel<<<dim3(Sq / 16, Bq), 256>>>(encpart, q, W2, b2, out_logits);

    // 8. masked log_softmax in place
    lsm_kernel<<<(Bq * Tq) / 8, 256>>>(out_logits, mask);

    (void)in_sizes; (void)n_in; (void)out_size; (void)state;
}

// round 17
// speedup vs baseline: 1.0030x; 1.0030x over previous
#include <cuda_runtime.h>
#include <math.h>

#define Bq 64
#define Sq 256
#define Tq 128
#define Hq 512
#define Eq 512
#define G4q 2048

typedef unsigned long long ull;

// ---------------- scratch (static device memory; no allocations) ----------------
__device__ float g_xW[(size_t)Bq * Sq * G4q];     // x@W_ih^T + b_ih + b_hh, per (b,s)
__device__ float g_enc[(size_t)Bq * Sq * Hq];     // encoder hidden states (b*S+s, h)
__device__ float g_encpart[(size_t)Bq * Sq * Hq]; // enc_outs @ W1_enc^T + b1
__device__ float g_qbuf[(size_t)Bq * Tq * Hq];    // dec_h @ W1_dec^T
__device__ float g_hA[Bq * Hq];
__device__ float g_hB[Bq * Hq];
__device__ int   g_bar[4 * 384];                  // per m-group, per step arrival counters

__device__ __forceinline__ float sigmoidf_(float x) { return 1.0f / (1.0f + expf(-x)); }

__device__ __forceinline__ void fma2(ull& d, ull a, ull b) {
    asm("fma.rn.f32x2 %0, %1, %2, %0;" : "+l"(d) : "l"(a), "l"(b));
}
__device__ __forceinline__ float hsum2(ull a) {
    float lo = __uint_as_float((unsigned)(a & 0xffffffffu));
    float hi = __uint_as_float((unsigned)(a >> 32));
    return lo + hi;
}

// ---------------- init: broadcast h0 into hA; zero step barriers ----------------
__global__ void init_state_kernel(const float* __restrict__ h0) {
    int i = blockIdx.x * blockDim.x + threadIdx.x;
    if (i < Bq * Hq) g_hA[i] = h0[i & (Hq - 1)];
    int b = i - Bq * Hq;
    if (b >= 0 && b < 4 * 384) g_bar[b] = 0;
}

// ---------------- fp32 GEMM, 128x128 tile, BK=16 double-buffered, 8x8 split tile ----
//  C[m,n] = sum_k A[row(m),k] * Wt[n,k] + bias(+bias2)
// 256 threads. Thread (ty,tx): m in {ty*4+i, 64+ty*4+i}, n in {tx*4+j, 64+tx*4+j}.
__global__ __launch_bounds__(256) void gemm_bias(
    const float* __restrict__ A, const float* __restrict__ Wt,
    const int* __restrict__ rows,
    const float* __restrict__ bias, const float* __restrict__ bias2,
    float* __restrict__ C, int K, int ldb, int ldc)
{
    __shared__ __align__(16) float As[2][16][128];
    __shared__ __align__(16) float Bs[2][16][128];

    int m0 = blockIdx.x * 128;
    int n0 = blockIdx.y * 128;
    int t  = threadIdx.x;
    int ty = t >> 4;
    int tx = t & 15;

    float aLL[4][4], aLH[4][4], aHL[4][4], aHH[4][4];
#pragma unroll
    for (int i = 0; i < 4; i++)
#pragma unroll
        for (int j = 0; j < 4; j++) {
            aLL[i][j] = 0.f; aLH[i][j] = 0.f; aHL[i][j] = 0.f; aHH[i][j] = 0.f;
        }

    int aRow = t >> 1;            // 0..127
    int aCol = (t & 1) * 8;       // 0 or 8
    long arow = rows ? (long)rows[m0 + aRow] : (long)(m0 + aRow);
    const float* Aptr = A + arow * (long)K + aCol;
    const float* Bptr = Wt + (long)(n0 + aRow) * ldb + aCol;

    const int nk = K / 16;
    float4 aF0 = *(const float4*)(Aptr);
    float4 aF1 = *(const float4*)(Aptr + 4);
    float4 bF0 = *(const float4*)(Bptr);
    float4 bF1 = *(const float4*)(Bptr + 4);

    As[0][aCol + 0][aRow] = aF0.x; As[0][aCol + 1][aRow] = aF0.y;
    As[0][aCol + 2][aRow] = aF0.z; As[0][aCol + 3][aRow] = aF0.w;
    As[0][aCol + 4][aRow] = aF1.x; As[0][aCol + 5][aRow] = aF1.y;
    As[0][aCol + 6][aRow] = aF1.z; As[0][aCol + 7][aRow] = aF1.w;
    Bs[0][aCol + 0][aRow] = bF0.x; Bs[0][aCol + 1][aRow] = bF0.y;
    Bs[0][aCol + 2][aRow] = bF0.z; Bs[0][aCol + 3][aRow] = bF0.w;
    Bs[0][aCol + 4][aRow] = bF1.x; Bs[0][aCol + 5][aRow] = bF1.y;
    Bs[0][aCol + 6][aRow] = bF1.z; Bs[0][aCol + 7][aRow] = bF1.w;
    __syncthreads();

    int buf = 0;
    for (int kb = 0; kb < nk; ++kb) {
        if (kb + 1 < nk) {
            const float* ap = Aptr + (kb + 1) * 16;
            const float* bp = Bptr + (kb + 1) * 16;
            aF0 = *(const float4*)(ap);
            aF1 = *(const float4*)(ap + 4);
            bF0 = *(const float4*)(bp);
            bF1 = *(const float4*)(bp + 4);
        }
#pragma unroll
        for (int kk = 0; kk < 16; ++kk) {
            float4 a0 = *(const float4*)&As[buf][kk][ty * 4];
            float4 a1 = *(const float4*)&As[buf][kk][64 + ty * 4];
            float4 b0 = *(const float4*)&Bs[buf][kk][tx * 4];
            float4 b1 = *(const float4*)&Bs[buf][kk][64 + tx * 4];
            float am0[4] = {a0.x, a0.y, a0.z, a0.w};
            float am1[4] = {a1.x, a1.y, a1.z, a1.w};
            float bn0[4] = {b0.x, b0.y, b0.z, b0.w};
            float bn1[4] = {b1.x, b1.y, b1.z, b1.w};
#pragma unroll
            for (int i = 0; i < 4; i++)
#pragma unroll
                for (int j = 0; j < 4; j++) {
                    aLL[i][j] = fmaf(am0[i], bn0[j], aLL[i][j]);
                    aLH[i][j] = fmaf(am0[i], bn1[j], aLH[i][j]);
                    aHL[i][j] = fmaf(am1[i], bn0[j], aHL[i][j]);
                    aHH[i][j] = fmaf(am1[i], bn1[j], aHH[i][j]);
                }
        }
        if (kb + 1 < nk) {
            int nb = buf ^ 1;
            As[nb][aCol + 0][aRow] = aF0.x; As[nb][aCol + 1][aRow] = aF0.y;
            As[nb][aCol + 2][aRow] = aF0.z; As[nb][aCol + 3][aRow] = aF0.w;
            As[nb][aCol + 4][aRow] = aF1.x; As[nb][aCol + 5][aRow] = aF1.y;
            As[nb][aCol + 6][aRow] = aF1.z; As[nb][aCol + 7][aRow] = aF1.w;
            Bs[nb][aCol + 0][aRow] = bF0.x; Bs[nb][aCol + 1][aRow] = bF0.y;
            Bs[nb][aCol + 2][aRow] = bF0.z; Bs[nb][aCol + 3][aRow] = bF0.w;
            Bs[nb][aCol + 4][aRow] = bF1.x; Bs[nb][aCol + 5][aRow] = bF1.y;
            Bs[nb][aCol + 6][aRow] = bF1.z; Bs[nb][aCol + 7][aRow] = bF1.w;
            __syncthreads();
            buf = nb;
        }
    }

    float bbL[4], bbH[4];
#pragma unroll
    for (int j = 0; j < 4; j++) {
        int nL = n0 + tx * 4 + j;
        int nH = nL + 64;
        float vL = 0.f, vH = 0.f;
        if (bias)  { vL += bias[nL];  vH += bias[nH]; }
        if (bias2) { vL += bias2[nL]; vH += bias2[nH]; }
        bbL[j] = vL; bbH[j] = vH;
    }
#pragma unroll
    for (int i = 0; i < 4; i++) {
        long rowL = (long)(m0 + ty * 4 + i) * ldc + n0 + tx * 4;
        long rowH = (long)(m0 + 64 + ty * 4 + i) * ldc + n0 + tx * 4;
        float4 oLL = make_float4(aLL[i][0] + bbL[0], aLL[i][1] + bbL[1],
                                 aLL[i][2] + bbL[2], aLL[i][3] + bbL[3]);
        float4 oLH = make_float4(aLH[i][0] + bbH[0], aLH[i][1] + bbH[1],
                                 aLH[i][2] + bbH[2], aLH[i][3] + bbH[3]);
        float4 oHL = make_float4(aHL[i][0] + bbL[0], aHL[i][1] + bbL[1],
                                 aHL[i][2] + bbL[2], aHL[i][3] + bbL[3]);
        float4 oHH = make_float4(aHH[i][0] + bbH[0], aHH[i][1] + bbH[1],
                                 aHH[i][2] + bbH[2], aHH[i][3] + bbH[3]);
        *(float4*)&C[rowL]      = oLL;
        *(float4*)&C[rowL + 64] = oLH;
        *(float4*)&C[rowH]      = oHL;
        *(float4*)&C[rowH + 64] = oHH;
    }
}

// ---------------- persistent fused LSTM recurrence (register-tiled, R10 compute) -----
// Grid: 128 CTAs x 256 threads. CTA (mb, jb): m-block = 16 batches, j-slice = 16 cols.
// Compute thread (ks, jj, mb2): 4 gates x 4 m over k-quarter ks; partials in ex[4][64*17].
#define WSTR 516
#define EXSZ (64 * 17)
#define SMEM_PERS ((64 * WSTR + 16 * WSTR + 4 * EXSZ) * 4)

__device__ __forceinline__ void load_wslice(float* ws, const float* __restrict__ W,
                                            int j0, int tid) {
    for (int idx = tid; idx < 64 * 128; idx += 256) {
        int r = idx >> 7;          // 0..63
        int k16 = idx & 127;       // float4 index
        int n = (r >> 4) * Hq + j0 + (r & 15);
        float4 v = *(const float4*)(W + (size_t)n * Hq + k16 * 4);
        *(float4*)(ws + r * WSTR + k16 * 4) = v;
    }
}

__global__ __launch_bounds__(256, 1) void lstm_persistent(
    const float* __restrict__ xW,
    const float* __restrict__ eWhh, const float* __restrict__ dWhh,
    const float* __restrict__ dbih, const float* __restrict__ dbhh,
    const float* __restrict__ c0,
    float* __restrict__ enc, float* __restrict__ dec_out)
{
    extern __shared__ float smem[];
    float* ws = smem;
    float* hs = smem + 64 * WSTR;
    float* ex = smem + 64 * WSTR + 16 * WSTR;      // 4 k-quarter buffers of 64*17

    int tid = threadIdx.x;
    int bx = blockIdx.x;
    int mb = bx >> 5;          // 0..3  (m-group)
    int jb = bx & 31;          // 0..31
    int j0 = jb * 16;

    // compute-role mapping: ks = k-quarter, jj = gate column, mb2 = m phase
    int lane = tid & 31, wrp = tid >> 5;
    int ks = wrp >> 1;                           // 0..3
    int jj = ((wrp & 1) << 3) + (lane >> 2);     // 0..15
    int mb2 = lane & 3;                          // 0..3
    int kbase = ks * 32;                         // ulonglong2 offset into k
    const ulonglong2* wr0 = (const ulonglong2*)(ws + (0 * 16 + jj) * WSTR) + kbase;
    const ulonglong2* wr1 = (const ulonglong2*)(ws + (1 * 16 + jj) * WSTR) + kbase;
    const ulonglong2* wr2 = (const ulonglong2*)(ws + (2 * 16 + jj) * WSTR) + kbase;
    const ulonglong2* wr3 = (const ulonglong2*)(ws + (3 * 16 + jj) * WSTR) + kbase;
    const ulonglong2* hm0 = (const ulonglong2*)(hs + (mb2 + 0) * WSTR) + kbase;
    const ulonglong2* hm1 = (const ulonglong2*)(hs + (mb2 + 4) * WSTR) + kbase;
    const ulonglong2* hm2 = (const ulonglong2*)(hs + (mb2 + 8) * WSTR) + kbase;
    const ulonglong2* hm3 = (const ulonglong2*)(hs + (mb2 + 12) * WSTR) + kbase;
    float* exk = ex + ks * EXSZ;

    // epilogue-role mapping
    int em = tid >> 4;         // 0..15 local m
    int ejj = tid & 15;        // 0..15 local j
    int j = j0 + ejj;
    int mg = mb * 16 + em;     // global batch index
    float c_reg = c0[j];
    float bi = 0.f, bf = 0.f, bg = 0.f, bo = 0.f;

    load_wslice(ws, eWhh, j0, tid);

    for (int step = 0; step < Sq + Tq; ++step) {
        const bool encp = (step < Sq);
        if (step == Sq) {
            __syncthreads();
            load_wslice(ws, dWhh, j0, tid);
            bi = dbih[j]           + dbhh[j];
            bf = dbih[Hq + j]      + dbhh[Hq + j];
            bg = dbih[2 * Hq + j]  + dbhh[2 * Hq + j];
            bo = dbih[3 * Hq + j]  + dbhh[3 * Hq + j];
        }
        const float* hcur = (step & 1) ? g_hB : g_hA;
        float*       hnxt = (step & 1) ? g_hA : g_hB;

        // stage this m-block's h rows into smem (full 512 floats/row: 2048 float4s)
        {
            const float* src = hcur + (size_t)mb * 16 * Hq;
#pragma unroll
            for (int rr = 0; rr < 8; ++rr) {
                int lin = tid + 256 * rr;     // float4 slot 0..2047
                int row = lin >> 7;           // 0..15
                int c4  = lin & 127;          // 0..127
                float4 v = *(const float4*)(src + (size_t)row * Hq + c4 * 4);
                *(float4*)(hs + row * WSTR + c4 * 4) = v;
            }
        }
        // prefetch per-step additive term (xW for encoder, bias for decoder)
        float xw0, xw1, xw2, xw3;
        if (encp) {
            const float* xr = xW + ((size_t)mg * Sq + step) * G4q + j;
            xw0 = xr[0]; xw1 = xr[Hq]; xw2 = xr[2 * Hq]; xw3 = xr[3 * Hq];
        } else {
            xw0 = bi; xw1 = bf; xw2 = bg; xw3 = bo;
        }
        __syncthreads();

        // register tile: acc[g][i] over k-quarter; 8 LDS.128 + 32 FFMA2 per iter
        {
            ull acc[4][4];
#pragma unroll
            for (int g = 0; g < 4; g++)
#pragma unroll
                for (int i = 0; i < 4; i++) acc[g][i] = 0;

#pragma unroll 8
            for (int kk = 0; kk < 32; ++kk) {
                ulonglong2 wv0 = wr0[kk];
                ulonglong2 wv1 = wr1[kk];
                ulonglong2 wv2 = wr2[kk];
                ulonglong2 wv3 = wr3[kk];
                ulonglong2 hv0 = hm0[kk];
                ulonglong2 hv1 = hm1[kk];
                ulonglong2 hv2 = hm2[kk];
                ulonglong2 hv3 = hm3[kk];
                fma2(acc[0][0], hv0.x, wv0.x); fma2(acc[0][0], hv0.y, wv0.y);
                fma2(acc[0][1], hv1.x, wv0.x); fma2(acc[0][1], hv1.y, wv0.y);
                fma2(acc[0][2], hv2.x, wv0.x); fma2(acc[0][2], hv2.y, wv0.y);
                fma2(acc[0][3], hv3.x, wv0.x); fma2(acc[0][3], hv3.y, wv0.y);
                fma2(acc[1][0], hv0.x, wv1.x); fma2(acc[1][0], hv0.y, wv1.y);
                fma2(acc[1][1], hv1.x, wv1.x); fma2(acc[1][1], hv1.y, wv1.y);
                fma2(acc[1][2], hv2.x, wv1.x); fma2(acc[1][2], hv2.y, wv1.y);
                fma2(acc[1][3], hv3.x, wv1.x); fma2(acc[1][3], hv3.y, wv1.y);
                fma2(acc[2][0], hv0.x, wv2.x); fma2(acc[2][0], hv0.y, wv2.y);
                fma2(acc[2][1], hv1.x, wv2.x); fma2(acc[2][1], hv1.y, wv2.y);
                fma2(acc[2][2], hv2.x, wv2.x); fma2(acc[2][2], hv2.y, wv2.y);
                fma2(acc[2][3], hv3.x, wv2.x); fma2(acc[2][3], hv3.y, wv2.y);
                fma2(acc[3][0], hv0.x, wv3.x); fma2(acc[3][0], hv0.y, wv3.y);
                fma2(acc[3][1], hv1.x, wv3.x); fma2(acc[3][1], hv1.y, wv3.y);
                fma2(acc[3][2], hv2.x, wv3.x); fma2(acc[3][2], hv2.y, wv3.y);
                fma2(acc[3][3], hv3.x, wv3.x); fma2(acc[3][3], hv3.y, wv3.y);
            }
            // write partials: exk[(g*16+jj)*17 + m], m = mb2 + 4i
#pragma unroll
            for (int g = 0; g < 4; g++)
#pragma unroll
                for (int i = 0; i < 4; i++)
                    exk[(g * 16 + jj) * 17 + (mb2 + 4 * i)] = hsum2(acc[g][i]);
        }
        __syncthreads();

        // epilogue: thread (em, ejj); combine 4 k-quarters
        {
            int i0 = (0 * 16 + ejj) * 17 + em;
            int i1 = (1 * 16 + ejj) * 17 + em;
            int i2 = (2 * 16 + ejj) * 17 + em;
            int i3 = (3 * 16 + ejj) * 17 + em;
            float vi = (ex[i0] + ex[i0 + EXSZ]) + (ex[i0 + 2 * EXSZ] + ex[i0 + 3 * EXSZ]) + xw0;
            float vf = (ex[i1] + ex[i1 + EXSZ]) + (ex[i1 + 2 * EXSZ] + ex[i1 + 3 * EXSZ]) + xw1;
            float vg = (ex[i2] + ex[i2 + EXSZ]) + (ex[i2 + 2 * EXSZ] + ex[i2 + 3 * EXSZ]) + xw2;
            float vo = (ex[i3] + ex[i3 + EXSZ]) + (ex[i3 + 2 * EXSZ] + ex[i3 + 3 * EXSZ]) + xw3;
            float cn = sigmoidf_(vf) * c_reg + sigmoidf_(vi) * tanhf(vg);
            float hn = sigmoidf_(vo) * tanhf(cn);
            c_reg = cn;
            hnxt[(size_t)mg * Hq + j] = hn;
            if (encp) enc[((size_t)mg * Sq + step) * Hq + j] = hn;
            else      dec_out[((size_t)mg * Tq + (step - Sq)) * Hq + j] = hn;
        }

        if (step == Sq + Tq - 1) break;   // nothing reads the final h: skip barrier

        // group barrier (32 CTAs sharing this m-block)
        __syncthreads();
        if (tid == 0) {
            int* bar = &g_bar[mb * 384 + step];
            asm volatile("red.release.gpu.global.add.s32 [%0], 1;" :: "l"(bar) : "memory");
            int v;
            do {
                asm volatile("ld.acquire.gpu.global.b32 %0, [%1];" : "=r"(v) : "l"(bar) : "memory");
            } while (v < 32);
        }
        __syncthreads();
    }
}

// ---------------- scoring: score[b,t,s] = b2 + sum_h W2[h]*relu(encpart[b,s,h]+q[b,t,h]) ----
__global__ __launch_bounds__(256) void score_kernel(
    const float* __restrict__ encpart, const float* __restrict__ q,
    const float* __restrict__ W2, const float* __restrict__ b2,
    float* __restrict__ out)
{
    __shared__ __align__(16) float qs[16][512];
    int b = blockIdx.y;
    int s0 = blockIdx.x * 16;
    int t = threadIdx.x;
    int warp = t >> 5;
    int lane = t & 31;

    float w2r[16], e0[16], e1[16];
    const float* ep = encpart + ((long)b * Sq + s0 + warp * 2) * Hq;
#pragma unroll
    for (int i = 0; i < 16; i++) {
        w2r[i] = W2[lane + 32 * i];
        e0[i] = ep[lane + 32 * i];
        e1[i] = ep[Hq + lane + 32 * i];
    }
    float b2v = b2[0];

    for (int tc = 0; tc < Tq / 16; ++tc) {
        __syncthreads();
        const float* qp = q + ((long)b * Tq + tc * 16) * Hq;
#pragma unroll
        for (int rr = 0; rr < 8; rr++) {
            int lin = t + 256 * rr;
            int tt = lin >> 7;
            int off = (lin & 127) * 4;
            *(float4*)&qs[tt][off] = *(const float4*)(qp + (long)tt * Hq + off);
        }
        __syncthreads();
#pragma unroll 4
        for (int tt = 0; tt < 16; ++tt) {
            float a0 = 0.0f, a1 = 0.0f;
#pragma unroll
            for (int i = 0; i < 16; i++) {
                float qv = qs[tt][lane + 32 * i];
                float v0 = fmaxf(e0[i] + qv, 0.0f);
                float v1 = fmaxf(e1[i] + qv, 0.0f);
                a0 = fmaf(v0, w2r[i], a0);
                a1 = fmaf(v1, w2r[i], a1);
            }
#pragma unroll
            for (int o = 16; o; o >>= 1) {
                a0 += __shfl_xor_sync(0xffffffffu, a0, o);
                a1 += __shfl_xor_sync(0xffffffffu, a1, o);
            }
            if (lane == 0) {
                long row = ((long)b * Tq + tc * 16 + tt) * Sq + s0 + warp * 2;
                out[row] = a0 + b2v;
                out[row + 1] = a1 + b2v;
            }
        }
    }
}

// ---------------- masked log_softmax over s (in place); mask is int32 ----------------
__global__ __launch_bounds__(256) void lsm_kernel(float* __restrict__ io,
                                                  const int* __restrict__ mask)
{
    int row = blockIdx.x * 8 + (threadIdx.x >> 5);
    int lane = threadIdx.x & 31;
    int b = row / Tq;
    const int* mrow = mask + (long)b * Sq;
    float* x = io + (long)row * Sq;

    float v[8];
    float mx = -INFINITY;
#pragma unroll
    for (int i = 0; i < 8; i++) {
        int s = lane + 32 * i;
        float xv = x[s];
        v[i] = (mrow[s] != 0) ? xv : -INFINITY;
        mx = fmaxf(mx, v[i]);
    }
#pragma unroll
    for (int o = 16; o; o >>= 1) mx = fmaxf(mx, __shfl_xor_sync(0xffffffffu, mx, o));
    float sum = 0.0f;
#pragma unroll
    for (int i = 0; i < 8; i++) sum += expf(v[i] - mx);
#pragma unroll
    for (int o = 16; o; o >>= 1) sum += __shfl_xor_sync(0xffffffffu, sum, o);
    float lse = mx + logf(sum);
#pragma unroll
    for (int i = 0; i < 8; i++) {
        int s = lane + 32 * i;
        x[s] = v[i] - lse;
    }
}

// ---------------- launch ----------------
extern "C" void kernel_launch(void* const* d_in, const int* in_sizes, int n_in,
                              void* d_out, int out_size)
{
    const int*   state = (const int*)d_in[0];
    const int*   mask  = (const int*)d_in[1];
    const float* emb  = (const float*)d_in[3];
    const float* eWih = (const float*)d_in[4];
    const float* eWhh = (const float*)d_in[5];
    const float* ebih = (const float*)d_in[6];
    const float* ebhh = (const float*)d_in[7];
    const float* h0   = (const float*)d_in[8];
    const float* c0   = (const float*)d_in[9];
    const float* dWhh = (const float*)d_in[11];
    const float* dbih = (const float*)d_in[12];
    const float* dbhh = (const float*)d_in[13];
    const float* W1   = (const float*)d_in[14];
    const float* b1   = (const float*)d_in[15];
    const float* W2   = (const float*)d_in[16];
    const float* b2   = (const float*)d_in[17];

    float* out_logits = (float*)d_out;
    float* out_dec    = out_logits + (size_t)Bq * Tq * Sq;

    float *xW, *enc, *encpart, *q;
    cudaGetSymbolAddress((void**)&xW, g_xW);
    cudaGetSymbolAddress((void**)&enc, g_enc);
    cudaGetSymbolAddress((void**)&encpart, g_encpart);
    cudaGetSymbolAddress((void**)&q, g_qbuf);

    static int smem_set = 0;
    if (!smem_set) {
        cudaFuncSetAttribute(lstm_persistent,
                             cudaFuncAttributeMaxDynamicSharedMemorySize, SMEM_PERS);
        smem_set = 1;
    }

    // 1. init h (broadcast) + zero barriers
    init_state_kernel<<<(Bq * Hq + 4 * 384 + 255) / 256, 256>>>(h0);

    // 2. xW = emb[state] @ enc_W_ih^T + (b_ih + b_hh)     (M=16384, N=2048, K=512)
    gemm_bias<<<dim3((Bq * Sq) / 128, G4q / 128), 256>>>(
        emb, eWih, state, ebih, ebhh, xW, Eq, Eq, G4q);

    // 3+5. full recurrence (256 encoder + 128 decoder steps) in one persistent kernel
    lstm_persistent<<<128, 256, SMEM_PERS>>>(xW, eWhh, dWhh, dbih, dbhh, c0,
                                             enc, out_dec);

    // 4. enc_part = enc_outs @ W1_enc^T + b1   (M=16384, N=512, K=512; W1 ld=1024)
    gemm_bias<<<dim3((Bq * Sq) / 128, Hq / 128), 256>>>(
        enc, W1, nullptr, b1, nullptr, encpart, Hq, Hq * 2, Hq);

    // 6. q = dec_hs @ W1_dec^T                 (M=8192, N=512, K=512)
    gemm_bias<<<dim3((Bq * Tq) / 128, Hq / 128), 256>>>(
        out_dec, W1 + Hq, nullptr, nullptr, nullptr, q, Hq, Hq * 2, Hq);

    // 7. scores -> out_logits (raw)
    score_kernel<<<dim3(Sq / 16, Bq), 256>>>(encpart, q, W2, b2, out_logits);

    // 8. masked log_softmax in place
    lsm_kernel<<<(Bq * Tq) / 8, 256>>>(out_logits, mask);

    (void)in_sizes; (void)n_in; (void)out_size; (void)state;
}